// round 6
// baseline (speedup 1.0000x reference)
#include <cuda_runtime.h>
#include <cuda_bf16.h>
#include <math_constants.h>

// TemporalAttentionPooling: out[b,d] = softmax_l(mask ? <seq[b,l,:],q>/sqrt(D) : -inf) . seq[b,l,d]
// B=32, L=4096, D=1024. Single-pass online softmax, warp-per-row-chunk,
// masked rows (weight==0) skipped entirely -> ~half the HBM traffic.
//
// Robustness: inputs bound by element count (ordering-proof); mask dtype
// (int32 vs uint8 serialization of bool) auto-detected on device.

#define BB 32
#define LL 4096
#define DD 1024
#define PP 64            // partials per batch (warps per batch)
#define ROWS (LL / PP)   // 64 rows per warp

// Scratch (allocation-free rule: __device__ globals).
__device__ float g_part_m [BB * PP];
__device__ float g_part_se[BB * PP];
__device__ float g_part_acc[(size_t)BB * PP * DD];   // 8 MB
__device__ int   g_mask_is_u8;

// ---------------------------------------------------------------------------
// Mask dtype detector: scan the first BB*LL bytes (safe under both layouts).
// int32-serialized bool -> every byte at offset %4 != 0 is zero.
// uint8-serialized bool (random 0/1) -> ~50% of those bytes nonzero.
// Deterministic function of input bytes; runs every call (graph-safe).
// ---------------------------------------------------------------------------
__global__ void __launch_bounds__(1024)
tap_detect(const unsigned int* __restrict__ mw)   // mask viewed as words
{
    __shared__ int s_any;
    if (threadIdx.x == 0) s_any = 0;
    __syncthreads();
    int local = 0;
    // BB*LL bytes = BB*LL/4 words; bytes 1..3 of each word are offsets %4 != 0.
    for (int i = threadIdx.x; i < BB * LL / 4; i += 1024)
        if (mw[i] & 0xFFFFFF00u) local = 1;
    if (local) atomicOr(&s_any, 1);
    __syncthreads();
    if (threadIdx.x == 0) g_mask_is_u8 = s_any;
}

// ---------------------------------------------------------------------------
// Pass 1: grid = (B * PP / 8) blocks of 256 threads (8 warps).
// Warp (b, p) processes rows [p*ROWS, (p+1)*ROWS) of batch b with online
// softmax; accumulator (1024 floats) lives in registers (32 per lane).
// Lane k owns columns d = 4k + 128j, j = 0..7  -> float4 loads, fully coalesced.
// ---------------------------------------------------------------------------
__global__ void __launch_bounds__(256, 2)
tap_pass1(const float* __restrict__ seq,
          const void* __restrict__ mask_raw,
          const float* __restrict__ query)
{
    const int warp = threadIdx.x >> 5;
    const int lane = threadIdx.x & 31;
    const int b    = blockIdx.x >> 3;                 // 8 blocks per batch
    const int p    = ((blockIdx.x & 7) << 3) + warp;  // partial index 0..63
    const int row0 = p * ROWS;

    const bool u8 = (g_mask_is_u8 != 0);
    const unsigned char* m8  = (const unsigned char*)mask_raw;
    const int*           m32 = (const int*)mask_raw;
    const int midx0 = b * LL + row0;

    // Query fragment in registers.
    float4 qf[8];
    const float4* q4 = reinterpret_cast<const float4*>(query);
#pragma unroll
    for (int j = 0; j < 8; j++) qf[j] = q4[lane + 32 * j];

    float m  = -CUDART_INF_F;
    float se = 0.0f;
    float4 acc[8];
#pragma unroll
    for (int j = 0; j < 8; j++) acc[j] = make_float4(0.f, 0.f, 0.f, 0.f);

    const float* srow = seq + (size_t)b * LL * DD + (size_t)row0 * DD;

    for (int r = 0; r < ROWS; r++) {
        // Uniform (broadcast) mask read; skip dead rows: weight is exactly 0.
        const int alive = u8 ? (int)m8[midx0 + r] : m32[midx0 + r];
        if (alive == 0) continue;

        const float4* x4 = reinterpret_cast<const float4*>(srow + (size_t)r * DD);
        float4 x[8];
#pragma unroll
        for (int j = 0; j < 8; j++) x[j] = x4[lane + 32 * j];

        // Dot with query, warp-reduced.
        float s = 0.f;
#pragma unroll
        for (int j = 0; j < 8; j++) {
            s = fmaf(x[j].x, qf[j].x, s);
            s = fmaf(x[j].y, qf[j].y, s);
            s = fmaf(x[j].z, qf[j].z, s);
            s = fmaf(x[j].w, qf[j].w, s);
        }
#pragma unroll
        for (int o = 16; o > 0; o >>= 1)
            s += __shfl_xor_sync(0xffffffffu, s, o);
        s *= 0.03125f;   // 1/sqrt(1024)

        // Online softmax update.
        const float nm   = fmaxf(m, s);
        const float rold = __expf(m - nm);   // first row: exp(-inf) = 0
        const float w    = __expf(s - nm);
        se = fmaf(se, rold, w);
#pragma unroll
        for (int j = 0; j < 8; j++) {
            acc[j].x = fmaf(acc[j].x, rold, w * x[j].x);
            acc[j].y = fmaf(acc[j].y, rold, w * x[j].y);
            acc[j].z = fmaf(acc[j].z, rold, w * x[j].z);
            acc[j].w = fmaf(acc[j].w, rold, w * x[j].w);
        }
        m = nm;
    }

    // Write partial (coalesced float4 stores).
    float4* pacc = reinterpret_cast<float4*>(g_part_acc + (size_t)(b * PP + p) * DD);
#pragma unroll
    for (int j = 0; j < 8; j++) pacc[lane + 32 * j] = acc[j];
    if (lane == 0) {
        g_part_m [b * PP + p] = m;
        g_part_se[b * PP + p] = se;
    }
}

// ---------------------------------------------------------------------------
// Pass 2: one block per batch. Log-sum-exp merge of 64 partials, then the
// weighted sum of partial accumulators. 8 MB total read -> ~2 us.
// ---------------------------------------------------------------------------
__global__ void __launch_bounds__(256)
tap_pass2(float* __restrict__ out)
{
    const int b = blockIdx.x;
    const int t = threadIdx.x;

    __shared__ float s_coef[PP];
    __shared__ float s_wred[8];
    __shared__ float s_M, s_S;

    // Global max over the 64 partial maxima.
    float m = (t < PP) ? g_part_m[b * PP + t] : -CUDART_INF_F;
    float v = m;
#pragma unroll
    for (int o = 16; o > 0; o >>= 1)
        v = fmaxf(v, __shfl_xor_sync(0xffffffffu, v, o));
    if ((t & 31) == 0) s_wred[t >> 5] = v;
    __syncthreads();
    if (t == 0) {
        float M = s_wred[0];
#pragma unroll
        for (int i = 1; i < 8; i++) M = fmaxf(M, s_wred[i]);
        s_M = M;
    }
    __syncthreads();
    const float M = s_M;

    // Per-partial coefficient and total normalizer.
    float sei = 0.f;
    if (t < PP) {
        const float coef = (m == -CUDART_INF_F) ? 0.f : __expf(m - M);
        s_coef[t] = coef;
        sei = coef * g_part_se[b * PP + t];
    }
    float sv = sei;
#pragma unroll
    for (int o = 16; o > 0; o >>= 1)
        sv += __shfl_xor_sync(0xffffffffu, sv, o);
    if ((t & 31) == 0) s_wred[t >> 5] = sv;
    __syncthreads();
    if (t == 0) {
        float S = 0.f;
#pragma unroll
        for (int i = 0; i < 8; i++) S += s_wred[i];
        s_S = S;
    }
    __syncthreads();
    const float inv = 1.0f / s_S;

    // Weighted sum of partial accumulators: thread t owns d = t + 256*k.
    float a0 = 0.f, a1 = 0.f, a2 = 0.f, a3 = 0.f;
    const float* base = g_part_acc + (size_t)b * PP * DD;
#pragma unroll 4
    for (int i = 0; i < PP; i++) {
        const float c = s_coef[i];
        const float* pa = base + (size_t)i * DD;
        a0 = fmaf(c, pa[t      ], a0);
        a1 = fmaf(c, pa[t + 256], a1);
        a2 = fmaf(c, pa[t + 512], a2);
        a3 = fmaf(c, pa[t + 768], a3);
    }
    float* o = out + (size_t)b * DD;
    o[t      ] = a0 * inv;
    o[t + 256] = a1 * inv;
    o[t + 512] = a2 * inv;
    o[t + 768] = a3 * inv;
}

// ---------------------------------------------------------------------------
extern "C" void kernel_launch(void* const* d_in, const int* in_sizes, int n_in,
                              void* d_out, int out_size)
{
    // Bind inputs by element count (ordering-proof):
    //   sequence: 32*4096*1024 = 134217728, mask: 32*4096 = 131072, query: 1024
    const float* seq   = nullptr;
    const void*  mask  = nullptr;
    const float* query = nullptr;
    for (int i = 0; i < n_in; i++) {
        if      (in_sizes[i] == BB * LL * DD) seq   = (const float*)d_in[i];
        else if (in_sizes[i] == BB * LL)      mask  = d_in[i];
        else if (in_sizes[i] == DD)           query = (const float*)d_in[i];
    }
    float* out = (float*)d_out;
    (void)out_size;

    tap_detect<<<1, 1024>>>((const unsigned int*)mask);
    tap_pass1<<<BB * PP / 8, 256>>>(seq, mask, query);
    tap_pass2<<<BB, 256>>>(out);
}

// round 8
// speedup vs baseline: 1.2347x; 1.2347x over previous
#include <cuda_runtime.h>
#include <cuda_bf16.h>
#include <math_constants.h>

// TemporalAttentionPooling: out[b,d] = softmax_l(mask ? <seq[b,l,:],q>/sqrt(D) : -inf) . seq[b,l,d]
// B=32, L=4096, D=1024. Single-pass online softmax, warp-per-row-chunk,
// masked rows (weight==0) skipped entirely -> ~half the HBM traffic.
//
// R7: detect folded into pass1, warp mask-bitmap prefetch (ballot), split dot
// chains, deferred-rescale softmax, __ldcs streaming loads, 128-block pass2.

#define BB 32
#define LL 4096
#define DD 1024
#define PP 64            // partials per batch (warps per batch)
#define ROWS (LL / PP)   // 64 rows per warp

// Scratch (allocation-free rule: __device__ globals).
__device__ float g_part_m [BB * PP];
__device__ float g_part_se[BB * PP];
__device__ float g_part_acc[(size_t)BB * PP * DD];   // 8 MB

// ---------------------------------------------------------------------------
// Pass 1: 256 blocks x 256 threads (8 warps, 2 CTAs/SM).
// Warp (b, p) owns rows [p*64, p*64+64) of batch b.
// Lane k owns columns d = 4k + 128j, j = 0..7 -> float4, fully coalesced.
// ---------------------------------------------------------------------------
__global__ void __launch_bounds__(256, 2)
tap_pass1(const float* __restrict__ seq,
          const void* __restrict__ mask_raw,
          const float* __restrict__ query)
{
    // ---- inline mask-dtype detection (bool serialized as u8 vs int32) ----
    // Scan first 1024 words (4 KB, safe under both layouts). int32-bool has
    // every byte at offset %4!=0 zero; random u8-bool does not (P ~ 2^-3072).
    int any = 0;
    if (threadIdx.x < 256) {
        const uint4 v = reinterpret_cast<const uint4*>(mask_raw)[threadIdx.x];
        if ((v.x | v.y | v.z | v.w) & 0xFFFFFF00u) any = 1;
    }
    const bool u8 = (__syncthreads_or(any) != 0);

    const int warp = threadIdx.x >> 5;
    const int lane = threadIdx.x & 31;
    const int b    = blockIdx.x >> 3;                 // 8 blocks per batch
    const int p    = ((blockIdx.x & 7) << 3) + warp;  // partial index 0..63
    const int row0 = p * ROWS;
    const int midx0 = b * LL + row0;

    // ---- warp mask bitmap: two 32-bit maps built with ballots ----
    // u8   : maskA bit l -> row 2l,   maskB bit l -> row 2l+1
    // int32: maskA bit l -> row l,    maskB bit l -> row 32+l
    unsigned maskA, maskB;
    if (u8) {
        const unsigned short v =
            reinterpret_cast<const unsigned short*>(mask_raw)[(midx0 >> 1) + lane];
        maskA = __ballot_sync(0xffffffffu, (v & 0x00FFu) != 0);
        maskB = __ballot_sync(0xffffffffu, (v & 0xFF00u) != 0);
    } else {
        const int* m32 = reinterpret_cast<const int*>(mask_raw) + midx0;
        maskA = __ballot_sync(0xffffffffu, m32[lane]      != 0);
        maskB = __ballot_sync(0xffffffffu, m32[lane + 32] != 0);
    }

    // Query fragment in registers (lane-dependent, warp-invariant).
    float4 qf[8];
    const float4* q4 = reinterpret_cast<const float4*>(query);
#pragma unroll
    for (int j = 0; j < 8; j++) qf[j] = q4[lane + 32 * j];

    float m  = -CUDART_INF_F;
    float se = 0.0f;
    float4 acc[8];
#pragma unroll
    for (int j = 0; j < 8; j++) acc[j] = make_float4(0.f, 0.f, 0.f, 0.f);

    const float4* srow4 =
        reinterpret_cast<const float4*>(seq + (size_t)b * LL * DD + (size_t)row0 * DD) + lane;

    // Online softmax is order-independent: iterate maskA rows then maskB rows.
#pragma unroll 1
    for (int half = 0; half < 2; half++) {
        unsigned mk = half ? maskB : maskA;
        while (mk) {
            const int l = __ffs(mk) - 1;
            mk &= mk - 1;
            const int r = u8 ? (2 * l + half) : (l + 32 * half);

            // 8 streaming float4 loads (512B warp wavefronts, MLP=8).
            const float4* x4 = srow4 + (size_t)r * (DD / 4);
            float4 x[8];
#pragma unroll
            for (int j = 0; j < 8; j++) x[j] = __ldcs(x4 + 32 * j);

            // Dot with query: 4 parallel FMA chains.
            float s0 = 0.f, s1 = 0.f, s2 = 0.f, s3 = 0.f;
#pragma unroll
            for (int j = 0; j < 8; j++) {
                s0 = fmaf(x[j].x, qf[j].x, s0);
                s1 = fmaf(x[j].y, qf[j].y, s1);
                s2 = fmaf(x[j].z, qf[j].z, s2);
                s3 = fmaf(x[j].w, qf[j].w, s3);
            }
            float s = (s0 + s1) + (s2 + s3);
#pragma unroll
            for (int o = 16; o > 0; o >>= 1)
                s += __shfl_xor_sync(0xffffffffu, s, o);
            s *= 0.03125f;   // 1/sqrt(1024)

            // Deferred-rescale online softmax (branch is warp-uniform).
            if (s > m) {
                const float rold = __expf(m - s);   // first row: exp(-inf)=0
                se = fmaf(se, rold, 1.0f);
#pragma unroll
                for (int j = 0; j < 8; j++) {       // w = 1
                    acc[j].x = fmaf(acc[j].x, rold, x[j].x);
                    acc[j].y = fmaf(acc[j].y, rold, x[j].y);
                    acc[j].z = fmaf(acc[j].z, rold, x[j].z);
                    acc[j].w = fmaf(acc[j].w, rold, x[j].w);
                }
                m = s;
            } else {
                const float w = __expf(s - m);
                se += w;
#pragma unroll
                for (int j = 0; j < 8; j++) {
                    acc[j].x = fmaf(w, x[j].x, acc[j].x);
                    acc[j].y = fmaf(w, x[j].y, acc[j].y);
                    acc[j].z = fmaf(w, x[j].z, acc[j].z);
                    acc[j].w = fmaf(w, x[j].w, acc[j].w);
                }
            }
        }
    }

    // Write partial (coalesced float4 stores).
    float4* pacc = reinterpret_cast<float4*>(g_part_acc + (size_t)(b * PP + p) * DD);
#pragma unroll
    for (int j = 0; j < 8; j++) pacc[lane + 32 * j] = acc[j];
    if (lane == 0) {
        g_part_m [b * PP + p] = m;
        g_part_se[b * PP + p] = se;
    }
}

// ---------------------------------------------------------------------------
// Pass 2: grid (B, 4), 256 threads. Block (b,q) handles d in [q*256,(q+1)*256).
// LSE-merge of 64 partials, then weighted sum; 64 KB read per block.
// ---------------------------------------------------------------------------
__global__ void __launch_bounds__(256)
tap_pass2(float* __restrict__ out)
{
    const int b = blockIdx.x;
    const int q = blockIdx.y;
    const int t = threadIdx.x;

    __shared__ float s_coef[PP];
    __shared__ float s_wred[8];
    __shared__ float s_M, s_S;

    // Global max over the 64 partial maxima.
    float m = (t < PP) ? g_part_m[b * PP + t] : -CUDART_INF_F;
    float v = m;
#pragma unroll
    for (int o = 16; o > 0; o >>= 1)
        v = fmaxf(v, __shfl_xor_sync(0xffffffffu, v, o));
    if ((t & 31) == 0) s_wred[t >> 5] = v;
    __syncthreads();
    if (t == 0) {
        float M = s_wred[0];
#pragma unroll
        for (int i = 1; i < 8; i++) M = fmaxf(M, s_wred[i]);
        s_M = M;
    }
    __syncthreads();
    const float M = s_M;

    // Per-partial coefficient and total normalizer.
    float sei = 0.f;
    if (t < PP) {
        const float coef = (m == -CUDART_INF_F) ? 0.f : __expf(m - M);
        s_coef[t] = coef;
        sei = coef * g_part_se[b * PP + t];
    }
    float sv = sei;
#pragma unroll
    for (int o = 16; o > 0; o >>= 1)
        sv += __shfl_xor_sync(0xffffffffu, sv, o);
    if ((t & 31) == 0) s_wred[t >> 5] = sv;
    __syncthreads();
    if (t == 0) {
        float S = 0.f;
#pragma unroll
        for (int i = 0; i < 8; i++) S += s_wred[i];
        s_S = S;
    }
    __syncthreads();
    const float inv = 1.0f / s_S;

    // Weighted sum over 64 partials for this block's 256 columns (MLP=4).
    const int d = q * 256 + t;
    const float* base = g_part_acc + (size_t)b * PP * DD + d;
    float a0 = 0.f, a1 = 0.f, a2 = 0.f, a3 = 0.f;
#pragma unroll
    for (int i = 0; i < PP; i += 4) {
        a0 = fmaf(s_coef[i    ], base[(size_t)(i    ) * DD], a0);
        a1 = fmaf(s_coef[i + 1], base[(size_t)(i + 1) * DD], a1);
        a2 = fmaf(s_coef[i + 2], base[(size_t)(i + 2) * DD], a2);
        a3 = fmaf(s_coef[i + 3], base[(size_t)(i + 3) * DD], a3);
    }
    out[(size_t)b * DD + d] = ((a0 + a1) + (a2 + a3)) * inv;
}

// ---------------------------------------------------------------------------
extern "C" void kernel_launch(void* const* d_in, const int* in_sizes, int n_in,
                              void* d_out, int out_size)
{
    // Bind inputs by element count (ordering-proof):
    //   sequence: 134217728, mask: 131072, query: 1024
    const float* seq   = nullptr;
    const void*  mask  = nullptr;
    const float* query = nullptr;
    for (int i = 0; i < n_in; i++) {
        if      (in_sizes[i] == BB * LL * DD) seq   = (const float*)d_in[i];
        else if (in_sizes[i] == BB * LL)      mask  = d_in[i];
        else if (in_sizes[i] == DD)           query = (const float*)d_in[i];
    }
    float* out = (float*)d_out;
    (void)out_size;

    tap_pass1<<<BB * PP / 8, 256>>>(seq, mask, query);
    tap_pass2<<<dim3(BB, 4), 256>>>(out);
}